// round 1
// baseline (speedup 1.0000x reference)
#include <cuda_runtime.h>
#include <math.h>

// ---------------- problem constants ----------------
#define BB    1024   // batch
#define DIMC  512
#define D2C   1024
#define HIDC  2048
#define NBASE 30
#define KBIG  (NBASE * D2C)   // 30720

#define PI_F      3.14159265358979323846f
#define INV_EMB   36.3636363636363636f   // 1 / 0.0275
#define LN_EPS_F  1e-5f

// ---------------- scratch (device globals; no allocation) ----------------
__device__ float g_att[BB * NBASE];
__device__ float g_e[BB * D2C];
__device__ float g_hin[BB * D2C];
__device__ float g_X[(size_t)BB * KBIG];        // 126 MB
__device__ float g_rt[BB * D2C];
__device__ float g_h1[BB * HIDC];
__device__ float g_h2[BB * HIDC];
__device__ float g_x0[BB * D2C];
__device__ float g_xstack[2 * BB * D2C];        // [0,B): x_rtrans, [B,2B): x_mlp
__device__ float g_a[2 * BB * DIMC];
__device__ float g_s[2 * BB * D2C];

// ---------------- prep: tanh/scale transforms + gathers ----------------
__global__ void prep_kernel(const float* __restrict__ ax, const float* __restrict__ ag,
                            const int* __restrict__ idx,
                            const float* __restrict__ rel_att,
                            const float* __restrict__ rax, const float* __restrict__ rag) {
    int b = blockIdx.x;
    int t = threadIdx.x;
    int rid = idx[b];
    if (t < NBASE) {
        g_att[b * NBASE + t] = tanhf(rel_att[rid * NBASE + t] * INV_EMB) * PI_F;
    }
    for (int j = t; j < DIMC; j += 256) {
        float a = ax[b * DIMC + j];
        float g = ag[b * DIMC + j];
        g_e[b * D2C + j]        = a;
        g_e[b * D2C + DIMC + j] = g;
        float raxv = tanhf(rax[rid * DIMC + j] * INV_EMB) * PI_F;
        float ragv = tanhf(2.0f * (rag[rid * DIMC + j] * INV_EMB)) * (PI_F * 0.5f) + (PI_F * 0.5f);
        g_hin[b * D2C + j]        = a + raxv;
        g_hin[b * D2C + DIMC + j] = g + ragv;
    }
}

// ---------------- build X[b, r*D2+i] = att[b,r]*e[b,i] ----------------
__global__ void buildX_kernel() {
    __shared__ float es[D2C];
    __shared__ float as[NBASE];
    int b = blockIdx.x;
    int t = threadIdx.x;
    for (int j = t; j < D2C; j += 256) es[j] = g_e[b * D2C + j];
    if (t < NBASE) as[t] = g_att[b * NBASE + t];
    __syncthreads();
    float* Xr = g_X + (size_t)b * KBIG;
    for (int k = t; k < KBIG; k += 256) {
        Xr[k] = as[k >> 10] * es[k & 1023];
    }
}

// ---------------- generic fp32 SIMT GEMM ----------------
// C[m,n] = act( sum_k A[m,k] * Wsel + bias[n] )
//   TRANSB=true : W is (N,K) row-major, Wsel = W[n*K + k]
//   TRANSB=false: W is (K,N) row-major, Wsel = W[k*N + n]
// Requires M%64==0, N%64==0, K%16==0.
#define GBM 64
#define GBN 64
#define GBK 16

template <bool TRANSB, int ACT>
__global__ void gemm_kernel(const float* __restrict__ A, const float* __restrict__ W,
                            const float* __restrict__ bias, float* __restrict__ C,
                            int M, int N, int K) {
    __shared__ float As[GBK][GBM + 4];
    __shared__ float Bs[GBK][GBN + 4];

    int tid = threadIdx.x;
    int m0 = blockIdx.y * GBM;
    int n0 = blockIdx.x * GBN;
    int tx = tid & 15;
    int ty = tid >> 4;

    int arow = tid >> 2;          // 0..63
    int akq  = (tid & 3) << 2;    // 0,4,8,12

    float acc[4][4];
#pragma unroll
    for (int i = 0; i < 4; i++)
#pragma unroll
        for (int j = 0; j < 4; j++) acc[i][j] = 0.0f;

    for (int k0 = 0; k0 < K; k0 += GBK) {
        float4 av = *reinterpret_cast<const float4*>(&A[(size_t)(m0 + arow) * K + k0 + akq]);
        As[akq + 0][arow] = av.x;
        As[akq + 1][arow] = av.y;
        As[akq + 2][arow] = av.z;
        As[akq + 3][arow] = av.w;
        if (TRANSB) {
            float4 bv = *reinterpret_cast<const float4*>(&W[(size_t)(n0 + arow) * K + k0 + akq]);
            Bs[akq + 0][arow] = bv.x;
            Bs[akq + 1][arow] = bv.y;
            Bs[akq + 2][arow] = bv.z;
            Bs[akq + 3][arow] = bv.w;
        } else {
            int brow = tid >> 4;         // 0..15
            int bn   = (tid & 15) << 2;  // 0..60
            float4 bv = *reinterpret_cast<const float4*>(&W[(size_t)(k0 + brow) * N + n0 + bn]);
            *reinterpret_cast<float4*>(&Bs[brow][bn]) = bv;
        }
        __syncthreads();
#pragma unroll
        for (int k = 0; k < GBK; k++) {
            float4 a4 = *reinterpret_cast<const float4*>(&As[k][ty << 2]);
            float4 b4 = *reinterpret_cast<const float4*>(&Bs[k][tx << 2]);
            float ar[4] = {a4.x, a4.y, a4.z, a4.w};
            float br[4] = {b4.x, b4.y, b4.z, b4.w};
#pragma unroll
            for (int i = 0; i < 4; i++)
#pragma unroll
                for (int j = 0; j < 4; j++) acc[i][j] = fmaf(ar[i], br[j], acc[i][j]);
        }
        __syncthreads();
    }

#pragma unroll
    for (int i = 0; i < 4; i++) {
        int m = m0 + (ty << 2) + i;
#pragma unroll
        for (int j = 0; j < 4; j++) {
            int n = n0 + (tx << 2) + j;
            float v = acc[i][j];
            if (bias) v += bias[n];
            if (ACT == 1) v = fmaxf(v, 0.0f);
            C[(size_t)m * N + n] = v;
        }
    }
}

// ---------------- block reduction helper ----------------
__device__ __forceinline__ float block_sum(float val, float* red) {
    int t = threadIdx.x;
    red[t] = val;
    __syncthreads();
#pragma unroll
    for (int s = 128; s > 0; s >>= 1) {
        if (t < s) red[t] += red[t + s];
        __syncthreads();
    }
    float r = red[0];
    __syncthreads();
    return r;
}

// ---------------- LN (rtrans branch, folds att@rel_bias) ----------------
__global__ void ln_rtrans_kernel(const float* __restrict__ rel_bias) {
    __shared__ float as[NBASE];
    __shared__ float red[256];
    int b = blockIdx.x;
    int t = threadIdx.x;
    if (t < NBASE) as[t] = g_att[b * NBASE + t];
    __syncthreads();

    float v[4];
    float s = 0.0f;
#pragma unroll
    for (int u = 0; u < 4; u++) {
        int i = t + u * 256;
        float x = g_rt[b * D2C + i];
#pragma unroll 6
        for (int r = 0; r < NBASE; r++) x = fmaf(as[r], rel_bias[r * D2C + i], x);
        v[u] = x;
        s += x;
    }
    float mean = block_sum(s, red) * (1.0f / D2C);
    float d = 0.0f;
#pragma unroll
    for (int u = 0; u < 4; u++) {
        float dv = v[u] - mean;
        d += dv * dv;
    }
    float var = block_sum(d, red) * (1.0f / D2C);
    float inv = rsqrtf(var + LN_EPS_F);
#pragma unroll
    for (int u = 0; u < 4; u++) {
        int i = t + u * 256;
        g_xstack[b * D2C + i] = (v[u] - mean) * inv;
    }
}

// ---------------- LN (mlp branch) ----------------
__global__ void ln_mlp_kernel() {
    __shared__ float red[256];
    int b = blockIdx.x;
    int t = threadIdx.x;
    float v[4];
    float s = 0.0f;
#pragma unroll
    for (int u = 0; u < 4; u++) {
        int i = t + u * 256;
        v[u] = g_x0[b * D2C + i];
        s += v[u];
    }
    float mean = block_sum(s, red) * (1.0f / D2C);
    float d = 0.0f;
#pragma unroll
    for (int u = 0; u < 4; u++) {
        float dv = v[u] - mean;
        d += dv * dv;
    }
    float var = block_sum(d, red) * (1.0f / D2C);
    float inv = rsqrtf(var + LN_EPS_F);
#pragma unroll
    for (int u = 0; u < 4; u++) {
        int i = t + u * 256;
        g_xstack[(size_t)(BB + b) * D2C + i] = (v[u] - mean) * inv;
    }
}

// ---------------- fusion: softmax over 2 branches + output transforms ----------------
__global__ void fuse_kernel(float* __restrict__ out) {
    int b = blockIdx.x;
    int t = threadIdx.x;
    for (int o = t; o < D2C; o += 256) {
        float s0 = g_s[(size_t)b * D2C + o];
        float s1 = g_s[(size_t)(BB + b) * D2C + o];
        float p0 = 1.0f / (1.0f + expf(s1 - s0));
        float x = p0 * g_xstack[(size_t)b * D2C + o] +
                  (1.0f - p0) * g_xstack[(size_t)(BB + b) * D2C + o];
        if (o < DIMC) {
            out[b * DIMC + o] = tanhf(x) * PI_F;
        } else {
            out[BB * DIMC + b * DIMC + (o - DIMC)] =
                tanhf(2.0f * x) * (PI_F * 0.5f) + (PI_F * 0.5f);
        }
    }
}

// ---------------- launch ----------------
extern "C" void kernel_launch(void* const* d_in, const int* in_sizes, int n_in,
                              void* d_out, int out_size) {
    const float* ax       = (const float*)d_in[0];
    const float* ag       = (const float*)d_in[1];
    const int*   idx      = (const int*)d_in[2];
    const float* rel_base = (const float*)d_in[3];
    const float* rel_att  = (const float*)d_in[4];
    const float* rel_bias = (const float*)d_in[5];
    const float* rax      = (const float*)d_in[6];
    const float* rag      = (const float*)d_in[7];
    const float* W1  = (const float*)d_in[8];
    const float* b1  = (const float*)d_in[9];
    const float* W2  = (const float*)d_in[10];
    const float* b2  = (const float*)d_in[11];
    const float* W0  = (const float*)d_in[12];
    const float* b0  = (const float*)d_in[13];
    const float* Wa1 = (const float*)d_in[14];
    const float* ba1 = (const float*)d_in[15];
    const float* Wa2 = (const float*)d_in[16];
    const float* ba2 = (const float*)d_in[17];
    float* out = (float*)d_out;

    float *pX, *prt, *phin, *ph1, *ph2, *px0, *pxs, *pa, *ps;
    cudaGetSymbolAddress((void**)&pX,  g_X);
    cudaGetSymbolAddress((void**)&prt, g_rt);
    cudaGetSymbolAddress((void**)&phin, g_hin);
    cudaGetSymbolAddress((void**)&ph1, g_h1);
    cudaGetSymbolAddress((void**)&ph2, g_h2);
    cudaGetSymbolAddress((void**)&px0, g_x0);
    cudaGetSymbolAddress((void**)&pxs, g_xstack);
    cudaGetSymbolAddress((void**)&pa,  g_a);
    cudaGetSymbolAddress((void**)&ps,  g_s);

    prep_kernel<<<BB, 256>>>(ax, ag, idx, rel_att, rax, rag);
    buildX_kernel<<<BB, 256>>>();

    // G1: rtrans big GEMM — X(1024 x 30720) @ rel_base(30720 x 1024)
    gemm_kernel<false, 0><<<dim3(D2C / GBN, BB / GBM), 256>>>(pX, rel_base, nullptr, prt,
                                                              BB, D2C, KBIG);
    ln_rtrans_kernel<<<BB, 256>>>(rel_bias);

    // MLP chain
    gemm_kernel<true, 1><<<dim3(HIDC / GBN, BB / GBM), 256>>>(phin, W1, b1, ph1, BB, HIDC, D2C);
    gemm_kernel<true, 1><<<dim3(HIDC / GBN, BB / GBM), 256>>>(ph1, W2, b2, ph2, BB, HIDC, HIDC);
    gemm_kernel<true, 0><<<dim3(D2C / GBN, BB / GBM), 256>>>(ph2, W0, b0, px0, BB, D2C, HIDC);
    ln_mlp_kernel<<<BB, 256>>>();

    // attention fusion (both branches stacked: M = 2048)
    gemm_kernel<true, 1><<<dim3(DIMC / GBN, 2 * BB / GBM), 256>>>(pxs, Wa1, ba1, pa,
                                                                  2 * BB, DIMC, D2C);
    gemm_kernel<true, 0><<<dim3(D2C / GBN, 2 * BB / GBM), 256>>>(pa, Wa2, ba2, ps,
                                                                 2 * BB, D2C, DIMC);
    fuse_kernel<<<BB, 256>>>(out);
}

// round 2
// speedup vs baseline: 2.5050x; 2.5050x over previous
#include <cuda_runtime.h>
#include <math.h>
#include <stdint.h>

// ---------------- problem constants ----------------
#define BB    1024   // batch
#define DIMC  512
#define D2C   1024
#define HIDC  2048
#define NBASE 30
#define KBIG  (NBASE * D2C)   // 30720

#define PI_F      3.14159265358979323846f
#define INV_EMB   36.3636363636363636f   // 1 / 0.0275
#define LN_EPS_F  1e-5f

// ---------------- scratch (device globals; no allocation) ----------------
__device__ float g_att[BB * NBASE];
__device__ float g_e[BB * D2C];
__device__ float g_hin[BB * D2C];
__device__ float g_X[(size_t)BB * KBIG];          // 126 MB
__device__ float g_rt[2 * BB * D2C];              // split-K partials
__device__ float g_h1[BB * HIDC];
__device__ float g_h2[BB * HIDC];
__device__ float g_x0[BB * D2C];
__device__ float g_xstack[2 * BB * D2C];          // [0,B): x_rtrans, [B,2B): x_mlp
__device__ float g_a[2 * BB * DIMC];
__device__ float g_s[2 * BB * D2C];

// ---------------- helpers ----------------
__device__ __forceinline__ float tf32r(float x) {
    uint32_t r;
    asm("cvt.rna.tf32.f32 %0, %1;" : "=r"(r) : "f"(x));
    return __uint_as_float(r);
}

__device__ __forceinline__ void mma8(float* c, const uint32_t* a, const uint32_t* b) {
    asm volatile(
        "mma.sync.aligned.m16n8k8.row.col.f32.tf32.tf32.f32 "
        "{%0,%1,%2,%3},{%4,%5,%6,%7},{%8,%9},{%0,%1,%2,%3};"
        : "+f"(c[0]), "+f"(c[1]), "+f"(c[2]), "+f"(c[3])
        : "r"(a[0]), "r"(a[1]), "r"(a[2]), "r"(a[3]), "r"(b[0]), "r"(b[1]));
}

// ---------------- prep: tanh/scale transforms + gathers ----------------
__global__ void prep_kernel(const float* __restrict__ ax, const float* __restrict__ ag,
                            const int* __restrict__ idx,
                            const float* __restrict__ rel_att,
                            const float* __restrict__ rax, const float* __restrict__ rag) {
    int b = blockIdx.x;
    int t = threadIdx.x;
    int rid = idx[b];
    if (t < NBASE) {
        g_att[b * NBASE + t] = tanhf(rel_att[rid * NBASE + t] * INV_EMB) * PI_F;
    }
    for (int j = t; j < DIMC; j += 256) {
        float a = ax[b * DIMC + j];
        float g = ag[b * DIMC + j];
        g_e[b * D2C + j]        = a;
        g_e[b * D2C + DIMC + j] = g;
        float raxv = tanhf(rax[rid * DIMC + j] * INV_EMB) * PI_F;
        float ragv = tanhf(2.0f * (rag[rid * DIMC + j] * INV_EMB)) * (PI_F * 0.5f) + (PI_F * 0.5f);
        g_hin[b * D2C + j]        = a + raxv;
        g_hin[b * D2C + DIMC + j] = g + ragv;
    }
}

// ---------------- build X[b, r*D2+i] = att[b,r]*e[b,i] ----------------
__global__ void buildX_kernel() {
    __shared__ float es[D2C];
    __shared__ float as[NBASE];
    int b = blockIdx.x;
    int t = threadIdx.x;
    for (int j = t; j < D2C; j += 256) es[j] = g_e[b * D2C + j];
    if (t < NBASE) as[t] = g_att[b * NBASE + t];
    __syncthreads();
    float* Xr = g_X + (size_t)b * KBIG;
    for (int k = t; k < KBIG; k += 256) {
        Xr[k] = as[k >> 10] * es[k & 1023];
    }
}

// ---------------- tf32 tensor-core GEMM ----------------
// C[m,n] = act( sum_k A[m,k] * Wsel + bias[n] )
//   TRANSB=true : W is (N,K) row-major
//   TRANSB=false: W is (K,N) row-major
// Block tile: BM x 128, BK = 16. 256 threads = 8 warps (2 in M x 4 in N).
// Warp tile: (BM/2) x 32. Split-K via blockIdx.z (partials at C + z*M*N).
template <int BM, bool TRANSB, int ACT>
__global__ void __launch_bounds__(256)
tgemm(const float* __restrict__ A, const float* __restrict__ W,
      const float* __restrict__ bias, float* __restrict__ C,
      int M, int N, int K, int kChunk) {
    constexpr int MT = BM / 32;          // m16 tiles per warp
    // As: [m][k] with row stride 20 (conflict-free fragment reads)
    __shared__ float As[2][BM * 20];
    // Bs: TRANSB -> [n][k] stride 20 ; !TRANSB -> [k][n] stride 136
    __shared__ float Bs[2][2560];

    const int tid  = threadIdx.x;
    const int lane = tid & 31, wid = tid >> 5;
    const int wm = wid & 1, wn = wid >> 1;
    const int grp = lane >> 2, qid = lane & 3;
    const int m0 = blockIdx.y * BM, n0 = blockIdx.x * 128;
    const int kStart = blockIdx.z * kChunk;
    const float* Ab = A + (size_t)m0 * K + kStart;
    float* Cb = C + (size_t)blockIdx.z * M * N;

    float c[MT][4][4];
#pragma unroll
    for (int i = 0; i < MT; i++)
#pragma unroll
        for (int j = 0; j < 4; j++)
#pragma unroll
            for (int q = 0; q < 4; q++) c[i][j][q] = 0.0f;

    const int T = kChunk / 16;

    // global->reg load indices
    const int ar  = tid >> 2;           // 0..63
    const int akq = (tid & 3) << 2;     // 0,4,8,12
    const int bk  = tid >> 4;           // 0..15   (!TRANSB)
    const int bn  = (tid & 15) << 3;    // 0..120  (!TRANSB)

    float4 ra[2], rb[2];

    auto ldgA = [&](int t) {
        ra[0] = *(const float4*)(Ab + (size_t)ar * K + t * 16 + akq);
        if (BM == 128)
            ra[1] = *(const float4*)(Ab + (size_t)(ar + 64) * K + t * 16 + akq);
    };
    auto ldgB = [&](int t) {
        if (TRANSB) {
            rb[0] = *(const float4*)(W + (size_t)(n0 + ar) * K + kStart + t * 16 + akq);
            rb[1] = *(const float4*)(W + (size_t)(n0 + ar + 64) * K + kStart + t * 16 + akq);
        } else {
            const float* p = W + (size_t)(kStart + t * 16 + bk) * N + n0 + bn;
            rb[0] = *(const float4*)(p);
            rb[1] = *(const float4*)(p + 4);
        }
    };
    auto sts = [&](int buf) {
        float* Ap = As[buf];
        Ap[ar * 20 + akq + 0] = tf32r(ra[0].x);
        Ap[ar * 20 + akq + 1] = tf32r(ra[0].y);
        Ap[ar * 20 + akq + 2] = tf32r(ra[0].z);
        Ap[ar * 20 + akq + 3] = tf32r(ra[0].w);
        if (BM == 128) {
            Ap[(ar + 64) * 20 + akq + 0] = tf32r(ra[1].x);
            Ap[(ar + 64) * 20 + akq + 1] = tf32r(ra[1].y);
            Ap[(ar + 64) * 20 + akq + 2] = tf32r(ra[1].z);
            Ap[(ar + 64) * 20 + akq + 3] = tf32r(ra[1].w);
        }
        float* Bp = Bs[buf];
        if (TRANSB) {
            Bp[ar * 20 + akq + 0] = tf32r(rb[0].x);
            Bp[ar * 20 + akq + 1] = tf32r(rb[0].y);
            Bp[ar * 20 + akq + 2] = tf32r(rb[0].z);
            Bp[ar * 20 + akq + 3] = tf32r(rb[0].w);
            Bp[(ar + 64) * 20 + akq + 0] = tf32r(rb[1].x);
            Bp[(ar + 64) * 20 + akq + 1] = tf32r(rb[1].y);
            Bp[(ar + 64) * 20 + akq + 2] = tf32r(rb[1].z);
            Bp[(ar + 64) * 20 + akq + 3] = tf32r(rb[1].w);
        } else {
            Bp[bk * 136 + bn + 0] = tf32r(rb[0].x);
            Bp[bk * 136 + bn + 1] = tf32r(rb[0].y);
            Bp[bk * 136 + bn + 2] = tf32r(rb[0].z);
            Bp[bk * 136 + bn + 3] = tf32r(rb[0].w);
            Bp[bk * 136 + bn + 4] = tf32r(rb[1].x);
            Bp[bk * 136 + bn + 5] = tf32r(rb[1].y);
            Bp[bk * 136 + bn + 6] = tf32r(rb[1].z);
            Bp[bk * 136 + bn + 7] = tf32r(rb[1].w);
        }
    };

    ldgA(0);
    ldgB(0);
    sts(0);
    __syncthreads();

    for (int t = 0; t < T; t++) {
        int buf = t & 1;
        if (t + 1 < T) { ldgA(t + 1); ldgB(t + 1); }

        const float* Ap = As[buf];
        const float* Bp = Bs[buf];
#pragma unroll
        for (int k8 = 0; k8 < 16; k8 += 8) {
            uint32_t af[MT][4], bf[4][2];
#pragma unroll
            for (int mt = 0; mt < MT; mt++) {
                int r = (wm * (BM / 2) + mt * 16 + grp) * 20;
                af[mt][0] = __float_as_uint(Ap[r + k8 + qid]);
                af[mt][1] = __float_as_uint(Ap[r + 160 + k8 + qid]);       // +8 rows
                af[mt][2] = __float_as_uint(Ap[r + k8 + qid + 4]);
                af[mt][3] = __float_as_uint(Ap[r + 160 + k8 + qid + 4]);
            }
#pragma unroll
            for (int nt = 0; nt < 4; nt++) {
                int nn = wn * 32 + nt * 8 + grp;
                if (TRANSB) {
                    bf[nt][0] = __float_as_uint(Bp[nn * 20 + k8 + qid]);
                    bf[nt][1] = __float_as_uint(Bp[nn * 20 + k8 + qid + 4]);
                } else {
                    bf[nt][0] = __float_as_uint(Bp[(k8 + qid) * 136 + nn]);
                    bf[nt][1] = __float_as_uint(Bp[(k8 + qid + 4) * 136 + nn]);
                }
            }
#pragma unroll
            for (int mt = 0; mt < MT; mt++)
#pragma unroll
                for (int nt = 0; nt < 4; nt++) mma8(c[mt][nt], af[mt], bf[nt]);
        }
        __syncthreads();
        if (t + 1 < T) {
            sts(buf ^ 1);
            __syncthreads();
        }
    }

    // epilogue
#pragma unroll
    for (int mt = 0; mt < MT; mt++) {
#pragma unroll
        for (int nt = 0; nt < 4; nt++) {
            int row = m0 + wm * (BM / 2) + mt * 16 + grp;
            int col = n0 + wn * 32 + nt * 8 + qid * 2;
            float v0 = c[mt][nt][0], v1 = c[mt][nt][1];
            float v2 = c[mt][nt][2], v3 = c[mt][nt][3];
            if (bias) {
                float b0 = bias[col], b1 = bias[col + 1];
                v0 += b0; v1 += b1; v2 += b0; v3 += b1;
            }
            if (ACT == 1) {
                v0 = fmaxf(v0, 0.0f); v1 = fmaxf(v1, 0.0f);
                v2 = fmaxf(v2, 0.0f); v3 = fmaxf(v3, 0.0f);
            }
            *(float2*)(&Cb[(size_t)row * N + col])       = make_float2(v0, v1);
            *(float2*)(&Cb[(size_t)(row + 8) * N + col]) = make_float2(v2, v3);
        }
    }
}

// ---------------- block reduction helper ----------------
__device__ __forceinline__ float block_sum(float val, float* red) {
    int t = threadIdx.x;
    red[t] = val;
    __syncthreads();
#pragma unroll
    for (int s = 128; s > 0; s >>= 1) {
        if (t < s) red[t] += red[t + s];
        __syncthreads();
    }
    float r = red[0];
    __syncthreads();
    return r;
}

// ---------------- LN (rtrans branch: sum split-K partials + att@rel_bias) ----------------
__global__ void ln_rtrans_kernel(const float* __restrict__ rel_bias) {
    __shared__ float as[NBASE];
    __shared__ float red[256];
    int b = blockIdx.x;
    int t = threadIdx.x;
    if (t < NBASE) as[t] = g_att[b * NBASE + t];
    __syncthreads();

    float v[4];
    float s = 0.0f;
#pragma unroll
    for (int u = 0; u < 4; u++) {
        int i = t + u * 256;
        float x = g_rt[b * D2C + i] + g_rt[(size_t)(BB + b) * D2C + i];
#pragma unroll 6
        for (int r = 0; r < NBASE; r++) x = fmaf(as[r], rel_bias[r * D2C + i], x);
        v[u] = x;
        s += x;
    }
    float mean = block_sum(s, red) * (1.0f / D2C);
    float d = 0.0f;
#pragma unroll
    for (int u = 0; u < 4; u++) {
        float dv = v[u] - mean;
        d += dv * dv;
    }
    float var = block_sum(d, red) * (1.0f / D2C);
    float inv = rsqrtf(var + LN_EPS_F);
#pragma unroll
    for (int u = 0; u < 4; u++) {
        int i = t + u * 256;
        g_xstack[b * D2C + i] = (v[u] - mean) * inv;
    }
}

// ---------------- LN (mlp branch) ----------------
__global__ void ln_mlp_kernel() {
    __shared__ float red[256];
    int b = blockIdx.x;
    int t = threadIdx.x;
    float v[4];
    float s = 0.0f;
#pragma unroll
    for (int u = 0; u < 4; u++) {
        int i = t + u * 256;
        v[u] = g_x0[b * D2C + i];
        s += v[u];
    }
    float mean = block_sum(s, red) * (1.0f / D2C);
    float d = 0.0f;
#pragma unroll
    for (int u = 0; u < 4; u++) {
        float dv = v[u] - mean;
        d += dv * dv;
    }
    float var = block_sum(d, red) * (1.0f / D2C);
    float inv = rsqrtf(var + LN_EPS_F);
#pragma unroll
    for (int u = 0; u < 4; u++) {
        int i = t + u * 256;
        g_xstack[(size_t)(BB + b) * D2C + i] = (v[u] - mean) * inv;
    }
}

// ---------------- fusion: softmax over 2 branches + output transforms ----------------
__global__ void fuse_kernel(float* __restrict__ out) {
    int b = blockIdx.x;
    int t = threadIdx.x;
    for (int o = t; o < D2C; o += 256) {
        float s0 = g_s[(size_t)b * D2C + o];
        float s1 = g_s[(size_t)(BB + b) * D2C + o];
        float p0 = 1.0f / (1.0f + expf(s1 - s0));
        float x = p0 * g_xstack[(size_t)b * D2C + o] +
                  (1.0f - p0) * g_xstack[(size_t)(BB + b) * D2C + o];
        if (o < DIMC) {
            out[b * DIMC + o] = tanhf(x) * PI_F;
        } else {
            out[BB * DIMC + b * DIMC + (o - DIMC)] =
                tanhf(2.0f * x) * (PI_F * 0.5f) + (PI_F * 0.5f);
        }
    }
}

// ---------------- launch ----------------
extern "C" void kernel_launch(void* const* d_in, const int* in_sizes, int n_in,
                              void* d_out, int out_size) {
    const float* ax       = (const float*)d_in[0];
    const float* ag       = (const float*)d_in[1];
    const int*   idx      = (const int*)d_in[2];
    const float* rel_base = (const float*)d_in[3];
    const float* rel_att  = (const float*)d_in[4];
    const float* rel_bias = (const float*)d_in[5];
    const float* rax      = (const float*)d_in[6];
    const float* rag      = (const float*)d_in[7];
    const float* W1  = (const float*)d_in[8];
    const float* b1  = (const float*)d_in[9];
    const float* W2  = (const float*)d_in[10];
    const float* b2  = (const float*)d_in[11];
    const float* W0  = (const float*)d_in[12];
    const float* b0  = (const float*)d_in[13];
    const float* Wa1 = (const float*)d_in[14];
    const float* ba1 = (const float*)d_in[15];
    const float* Wa2 = (const float*)d_in[16];
    const float* ba2 = (const float*)d_in[17];
    float* out = (float*)d_out;

    float *pX, *prt, *phin, *ph1, *ph2, *px0, *pxs, *pa, *ps;
    cudaGetSymbolAddress((void**)&pX,   g_X);
    cudaGetSymbolAddress((void**)&prt,  g_rt);
    cudaGetSymbolAddress((void**)&phin, g_hin);
    cudaGetSymbolAddress((void**)&ph1,  g_h1);
    cudaGetSymbolAddress((void**)&ph2,  g_h2);
    cudaGetSymbolAddress((void**)&px0,  g_x0);
    cudaGetSymbolAddress((void**)&pxs,  g_xstack);
    cudaGetSymbolAddress((void**)&pa,   g_a);
    cudaGetSymbolAddress((void**)&ps,   g_s);

    prep_kernel<<<BB, 256>>>(ax, ag, idx, rel_att, rax, rag);
    buildX_kernel<<<BB, 256>>>();

    // G1: rtrans big GEMM — X(1024 x 30720) @ rel_base(30720 x 1024), split-K=2
    tgemm<128, false, 0><<<dim3(D2C / 128, BB / 128, 2), 256>>>(
        pX, rel_base, nullptr, prt, BB, D2C, KBIG, KBIG / 2);
    ln_rtrans_kernel<<<BB, 256>>>(rel_bias);

    // MLP chain
    tgemm<128, true, 1><<<dim3(HIDC / 128, BB / 128, 1), 256>>>(
        phin, W1, b1, ph1, BB, HIDC, D2C, D2C);
    tgemm<128, true, 1><<<dim3(HIDC / 128, BB / 128, 1), 256>>>(
        ph1, W2, b2, ph2, BB, HIDC, HIDC, HIDC);
    tgemm<64, true, 0><<<dim3(D2C / 128, BB / 64, 1), 256>>>(
        ph2, W0, b0, px0, BB, D2C, HIDC, HIDC);
    ln_mlp_kernel<<<BB, 256>>>();

    // attention fusion (both branches stacked: M = 2048)
    tgemm<64, true, 1><<<dim3(DIMC / 128, 2 * BB / 64, 1), 256>>>(
        pxs, Wa1, ba1, pa, 2 * BB, DIMC, D2C, D2C);
    tgemm<128, true, 0><<<dim3(D2C / 128, 2 * BB / 128, 1), 256>>>(
        pa, Wa2, ba2, ps, 2 * BB, D2C, DIMC, DIMC);
    fuse_kernel<<<BB, 256>>>(out);
}